// round 6
// baseline (speedup 1.0000x reference)
#include <cuda_runtime.h>
#include <math.h>
#include <stdint.h>

#define Bn 64
#define Ln 2048
#define Hn 128
#define Vn 32000

// ---------------- scratch (static device globals; no runtime allocation) ----
__device__ float  g_ff1[(size_t)Vn * 256];
__device__ float  g_x  [(size_t)Vn * Hn];
__device__ float  g_hn [(size_t)Vn * Hn];
__device__ float  g_kt [(size_t)Vn * Hn];
__device__ float  g_kn [(size_t)Vn * Hn];
__device__ float2 g_meta[Vn];            // (norm, ||kn||^2)
__device__ float  g_read[Bn * Hn];
__device__ float  g_tmp [Bn * Hn];
__device__ float  g_zero[256];           // zero-initialized: dummy bias

// packed fp32x2 FMA (Blackwell FFMA2 — only reachable via PTX fma.rn.f32x2)
__device__ __forceinline__ float2 ffma2(float2 a, float2 b, float2 c) {
    float2 d;
    asm("fma.rn.f32x2 %0, %1, %2, %3;"
        : "=l"(reinterpret_cast<unsigned long long&>(d))
        : "l"(reinterpret_cast<unsigned long long&>(a)),
          "l"(reinterpret_cast<unsigned long long&>(b)),
          "l"(reinterpret_cast<unsigned long long&>(c)));
    return d;
}

// async global->shared copies (no register landing; completion via groups)
__device__ __forceinline__ void cp_async16(void* sdst, const void* gsrc) {
    uint32_t sa = (uint32_t)__cvta_generic_to_shared(sdst);
    asm volatile("cp.async.cg.shared.global [%0], [%1], 16;" :: "r"(sa), "l"(gsrc));
}
__device__ __forceinline__ void cp_async8(void* sdst, const void* gsrc) {
    uint32_t sa = (uint32_t)__cvta_generic_to_shared(sdst);
    asm volatile("cp.async.ca.shared.global [%0], [%1], 8;" :: "r"(sa), "l"(gsrc));
}

// ---------------- generic fp32 GEMM (unchanged) ------------------------------
template <bool RELU, bool RESID>
__global__ void __launch_bounds__(256, 2) sgemm_tn(
    const float* __restrict__ A, const float* __restrict__ Bm,
    const float* __restrict__ bias, const float* __restrict__ resid,
    float* __restrict__ C, int Nn, int K)
{
    __shared__ float As[32][132];
    __shared__ float Bs[32][132];
    const int m0 = blockIdx.x * 128;
    const int n0 = blockIdx.y * 128;
    const int tid = threadIdx.x;
    const int tx = tid & 15;
    const int ty = tid >> 4;
    const int lrow = tid >> 3;       // 0..31
    const int lk   = (tid & 7) * 4;  // 0..28

    float2 acc2[8][4];
#pragma unroll
    for (int i = 0; i < 8; ++i)
#pragma unroll
        for (int j = 0; j < 4; ++j) acc2[i][j] = make_float2(0.f, 0.f);

    for (int k0 = 0; k0 < K; k0 += 32) {
#pragma unroll
        for (int p = 0; p < 4; ++p) {
            int row = lrow + p * 32;
            float4 av = *(const float4*)&A [(size_t)(m0 + row) * K + k0 + lk];
            As[lk + 0][row] = av.x; As[lk + 1][row] = av.y;
            As[lk + 2][row] = av.z; As[lk + 3][row] = av.w;
            float4 bv = *(const float4*)&Bm[(size_t)(n0 + row) * K + k0 + lk];
            Bs[lk + 0][row] = bv.x; Bs[lk + 1][row] = bv.y;
            Bs[lk + 2][row] = bv.z; Bs[lk + 3][row] = bv.w;
        }
        __syncthreads();
#pragma unroll 8
        for (int kk = 0; kk < 32; ++kk) {
            float4 a0 = *(const float4*)&As[kk][ty * 8];
            float4 a1 = *(const float4*)&As[kk][ty * 8 + 4];
            float4 b0 = *(const float4*)&Bs[kk][tx * 8];
            float4 b1 = *(const float4*)&Bs[kk][tx * 8 + 4];
            float a[8] = {a0.x, a0.y, a0.z, a0.w, a1.x, a1.y, a1.z, a1.w};
            float2 bb[4] = {make_float2(b0.x, b0.y), make_float2(b0.z, b0.w),
                            make_float2(b1.x, b1.y), make_float2(b1.z, b1.w)};
#pragma unroll
            for (int i = 0; i < 8; ++i) {
                float2 ai = make_float2(a[i], a[i]);
#pragma unroll
                for (int j = 0; j < 4; ++j)
                    acc2[i][j] = ffma2(ai, bb[j], acc2[i][j]);
            }
        }
        __syncthreads();
    }

#pragma unroll
    for (int i = 0; i < 8; ++i) {
        const int m = m0 + ty * 8 + i;
#pragma unroll
        for (int j = 0; j < 4; ++j) {
            const int n = n0 + tx * 8 + j * 2;
            float vx = acc2[i][j].x + bias[n];
            float vy = acc2[i][j].y + bias[n + 1];
            if (RELU) { vx = fmaxf(vx, 0.f); vy = fmaxf(vy, 0.f); }
            if (RESID) {
                vx += resid[(size_t)m * Nn + n];
                vy += resid[(size_t)m * Nn + n + 1];
            }
            C[(size_t)m * Nn + n]     = vx;
            C[(size_t)m * Nn + n + 1] = vy;
        }
    }
}

// ---------------- LayerNorm: one warp per row of 128 -------------------------
__global__ void __launch_bounds__(256) ln_kernel(
    const float* __restrict__ g, const float* __restrict__ bparm)
{
    const int lane = threadIdx.x & 31;
    const int row  = blockIdx.x * 8 + (threadIdx.x >> 5);
    float4 v = ((const float4*)(g_x + (size_t)row * Hn))[lane];
    float s = (v.x + v.y) + (v.z + v.w);
#pragma unroll
    for (int d = 16; d; d >>= 1) s += __shfl_xor_sync(0xffffffffu, s, d);
    const float mu = s * (1.0f / 128.0f);
    float dx = v.x - mu, dy = v.y - mu, dz = v.z - mu, dw = v.w - mu;
    float q = (dx * dx + dy * dy) + (dz * dz + dw * dw);
#pragma unroll
    for (int d = 16; d; d >>= 1) q += __shfl_xor_sync(0xffffffffu, q, d);
    const float rstd = rsqrtf(q * (1.0f / 128.0f) + 1e-5f);
    float4 gg = ((const float4*)g)[lane];
    float4 bb = ((const float4*)bparm)[lane];
    float4 o;
    o.x = fmaf(dx * rstd, gg.x, bb.x);
    o.y = fmaf(dy * rstd, gg.y, bb.y);
    o.z = fmaf(dz * rstd, gg.z, bb.z);
    o.w = fmaf(dw * rstd, gg.w, bb.w);
    ((float4*)(g_hn + (size_t)row * Hn))[lane] = o;
}

// ---------------- row normalize k-table: kn + packed meta --------------------
__global__ void __launch_bounds__(256) norm_kernel()
{
    const int lane = threadIdx.x & 31;
    const int row  = blockIdx.x * 8 + (threadIdx.x >> 5);
    float4 v = ((const float4*)(g_kt + (size_t)row * Hn))[lane];
    float q = (v.x * v.x + v.y * v.y) + (v.z * v.z + v.w * v.w);
#pragma unroll
    for (int d = 16; d; d >>= 1) q += __shfl_xor_sync(0xffffffffu, q, d);
    const float nrm = sqrtf(q);
    const float den = fmaxf(nrm, 1e-12f);
    const float inv = 1.0f / den;
    float4 o; o.x = v.x * inv; o.y = v.y * inv; o.z = v.z * inv; o.w = v.w * inv;
    ((float4*)(g_kn + (size_t)row * Hn))[lane] = o;
    if (lane == 0) g_meta[row] = make_float2(nrm, q * inv * inv);
}

// ---------------- pipelined memory-matrix scan: 1 CTA per batch --------------
// Rank-1-corrected recurrence:  vp_t = M_{t-2}.kn_t + g_{t-1}*rr_{t-1}*(kn_{t-1}.kn_t)
// Order per iter puts the gated update + next matvec BETWEEN the shuffle-chain
// issue and the partials STS, so the reduce/barrier latency hides under FFMA
// issue. Token feed: cp.async into an 8-slot ring, distance 4, wait_group 2.
__global__ void __launch_bounds__(256, 1) scan_kernel(const int* __restrict__ seq)
{
    __shared__ __align__(16) float  s_kn[8][128];
    __shared__ __align__(16) float2 s_meta[8];
    __shared__ int   s_seq[Ln];
    __shared__ __align__(16) float2 s_part[2][8];   // (energy, dot) per warp

    const int b    = blockIdx.x;
    const int tid  = threadIdx.x;
    const int r    = tid >> 1;
    const int hh   = tid & 1;
    const int off  = hh << 6;
    const int lane = tid & 31;
    const int wid  = tid >> 5;

    for (int i = tid; i < Ln; i += 256) s_seq[i] = seq[(size_t)b * Ln + i];

    float2 M2[32];
#pragma unroll
    for (int j = 0; j < 32; ++j) M2[j] = make_float2(0.f, 0.f);
    __syncthreads();

    // prologue: preload ring slots 0..3 (tokens 0..3) synchronously
    if (tid < 128) {
        int bi = tid >> 5, l2 = tid & 31;
        int tok = s_seq[bi];
        ((float4*)s_kn[bi])[l2] = ((const float4*)(g_kn + (size_t)tok * Hn))[l2];
    }
    if (tid < 4) s_meta[tid] = g_meta[s_seq[tid]];
    __syncthreads();

    float2 kk[32];                 // holds kn_{t+1} after iter t's reload
    float rr_prev = 0.f, kn2_prev = 1.f, a_next = 0.f;

    for (int t = 0; t < Ln - 1; ++t) {
        const int cs = t & 7, ns = (t + 1) & 7;
        const float a_t = a_next;

        // 1) gate + dot-correction from step t-1 partials (post-barrier)
        bool  gate  = false;
        float dcorr = 0.f;
        if (t > 0) {
            const float4* pp = (const float4*)s_part[(t - 1) & 1];
            float4 q0 = pp[0], q1 = pp[1], q2 = pp[2], q3 = pp[3];
            float te = ((q0.x + q0.z) + (q1.x + q1.z)) + ((q2.x + q2.z) + (q3.x + q3.z));
            dcorr    = ((q0.y + q0.w) + (q1.y + q1.w)) + ((q2.y + q2.w) + (q3.y + q3.w));
            gate = (te * kn2_prev * (1.0f / 16384.0f) >= 0.4f);
        }

        // 2) corrected vp and residual rr for step t
        const float2 meta = s_meta[cs];
        const float  kv   = s_kn[cs][r];
        const float  kvn  = s_kn[ns][r];
        float vp = a_t;
        if (gate) vp = fmaf(rr_prev, dcorr, vp);
        const float rr = fmaf(meta.x, kv, -vp);

        // 3) issue interleaved shuffle chains: e(t) and pd(t)=kn_t.kn_{t+1}
        float e  = rr * rr;
        float pd = kv * kvn;
#pragma unroll
        for (int d = 2; d <= 16; d <<= 1) {
            e  += __shfl_xor_sync(0xffffffffu, e,  d);
            pd += __shfl_xor_sync(0xffffffffu, pd, d);
        }

        // 4) gated rank-1 update from step t-1 (independent of chains above)
        if (gate) {
            const float4* kp = (const float4*)(s_kn[(t - 1) & 7] + off);
            const float2 rp = make_float2(rr_prev, rr_prev);
#pragma unroll
            for (int j = 0; j < 16; ++j) {
                float4 v = kp[j];
                M2[2 * j]     = ffma2(rp, make_float2(v.x, v.y), M2[2 * j]);
                M2[2 * j + 1] = ffma2(rp, make_float2(v.z, v.w), M2[2 * j + 1]);
            }
        }

        // 5) reload kk = kn_{t+1}
#pragma unroll
        for (int j = 0; j < 16; ++j) {
            float4 v = ((const float4*)(s_kn[ns] + off))[j];
            kk[2 * j]     = make_float2(v.x, v.y);
            kk[2 * j + 1] = make_float2(v.z, v.w);
        }

        // 6) matvec a(t+1) = M_{t-1}.kn_{t+1}
        float2 a0 = make_float2(0.f, 0.f), a1 = a0, a2 = a0, a3 = a0;
#pragma unroll
        for (int j = 0; j < 32; j += 4) {
            a0 = ffma2(M2[j + 0], kk[j + 0], a0);
            a1 = ffma2(M2[j + 1], kk[j + 1], a1);
            a2 = ffma2(M2[j + 2], kk[j + 2], a2);
            a3 = ffma2(M2[j + 3], kk[j + 3], a3);
        }
        float an = ((a0.x + a0.y) + (a1.x + a1.y)) + ((a2.x + a2.y) + (a3.x + a3.y));
        an += __shfl_xor_sync(0xffffffffu, an, 1);
        a_next = an;

        // 7) publish partials (chains resolved under the FFMA issue above)
        if (lane == 0) s_part[t & 1][wid] = make_float2(e, pd);

        // 8) async prefetch token t+4 into ring; keep 2 groups of slack
        if (tid < 32) {
            if (t + 4 < Ln) {
                const int pb = (t + 4) & 7;
                const int tok = s_seq[t + 4];
                cp_async16(&s_kn[pb][tid * 4], g_kn + (size_t)tok * Hn + tid * 4);
                if (tid == 0) cp_async8(&s_meta[pb], g_meta + tok);
            }
            asm volatile("cp.async.commit_group;" ::: "memory");
            asm volatile("cp.async.wait_group 2;" ::: "memory");
        }
        __syncthreads();   // the ONLY barrier per step

        rr_prev = rr; kn2_prev = meta.y;
    }

    // epilogue: gate for the final step, pending update, then read = M.q
    {
        const int tl = Ln - 2;   // last loop t
        const float4* pp = (const float4*)s_part[tl & 1];
        float4 q0 = pp[0], q1 = pp[1], q2 = pp[2], q3 = pp[3];
        float te = ((q0.x + q0.z) + (q1.x + q1.z)) + ((q2.x + q2.z) + (q3.x + q3.z));
        if (te * kn2_prev * (1.0f / 16384.0f) >= 0.4f) {
            const float4* kp = (const float4*)(s_kn[tl & 7] + off);
            const float2 rp = make_float2(rr_prev, rr_prev);
#pragma unroll
            for (int j = 0; j < 16; ++j) {
                float4 v = kp[j];
                M2[2 * j]     = ffma2(rp, make_float2(v.x, v.y), M2[2 * j]);
                M2[2 * j + 1] = ffma2(rp, make_float2(v.z, v.w), M2[2 * j + 1]);
            }
        }
        // kk holds kn_{Ln-1}; q = kn_{Ln-1} * norm_{Ln-1}
        float2 a0 = make_float2(0.f, 0.f), a1 = a0, a2 = a0, a3 = a0;
#pragma unroll
        for (int j = 0; j < 32; j += 4) {
            a0 = ffma2(M2[j + 0], kk[j + 0], a0);
            a1 = ffma2(M2[j + 1], kk[j + 1], a1);
            a2 = ffma2(M2[j + 2], kk[j + 2], a2);
            a3 = ffma2(M2[j + 3], kk[j + 3], a3);
        }
        float vp = ((a0.x + a0.y) + (a1.x + a1.y)) + ((a2.x + a2.y) + (a3.x + a3.y));
        vp += __shfl_xor_sync(0xffffffffu, vp, 1);
        if (hh == 0) g_read[b * Hn + r] = vp * s_meta[(Ln - 1) & 7].x;
    }
}

// ---------------- tmp = read @ rp_w^T + rp_b ---------------------------------
__global__ void __launch_bounds__(128) readrp_kernel(
    const float* __restrict__ rp_w, const float* __restrict__ rp_b)
{
    __shared__ float s_r[128];
    const int b = blockIdx.x;
    s_r[threadIdx.x] = g_read[b * Hn + threadIdx.x];
    __syncthreads();
    const int n = threadIdx.x;
    const float* wrow = rp_w + (size_t)n * Hn;
    float a0 = 0.f, a1 = 0.f, a2 = 0.f, a3 = 0.f;
#pragma unroll 8
    for (int j = 0; j < 128; j += 4) {
        a0 = fmaf(s_r[j + 0], wrow[j + 0], a0);
        a1 = fmaf(s_r[j + 1], wrow[j + 1], a1);
        a2 = fmaf(s_r[j + 2], wrow[j + 2], a2);
        a3 = fmaf(s_r[j + 3], wrow[j + 3], a3);
    }
    g_tmp[b * Hn + n] = (a0 + a1) + (a2 + a3) + rp_b[n];
}

// ---------------- logits: out[b][v] = tmp[b][:] . out_w[v][:] + out_b[v] -----
__global__ void __launch_bounds__(256) logits_kernel(
    const float* __restrict__ out_w, const float* __restrict__ out_b,
    float* __restrict__ outp)
{
    __shared__ __align__(16) float s_t[128][64];  // [j][b]
    for (int i = threadIdx.x; i < Bn * Hn; i += 256) {
        int b = i >> 7, j = i & 127;
        s_t[j][b] = g_tmp[i];
    }
    __syncthreads();

    const int v = blockIdx.x * 256 + threadIdx.x;
    const float4* wr = (const float4*)(out_w + (size_t)v * Hn);
    const float ob = out_b[v];
    float4 acc[16];
#pragma unroll
    for (int q = 0; q < 16; ++q) acc[q] = make_float4(ob, ob, ob, ob);

    for (int j4 = 0; j4 < 32; ++j4) {
        float4 w = wr[j4];
        float wj[4] = {w.x, w.y, w.z, w.w};
#pragma unroll
        for (int c = 0; c < 4; ++c) {
            const float4* tp = (const float4*)s_t[j4 * 4 + c];
#pragma unroll
            for (int q = 0; q < 16; ++q) {
                float4 t = tp[q];
                acc[q].x = fmaf(wj[c], t.x, acc[q].x);
                acc[q].y = fmaf(wj[c], t.y, acc[q].y);
                acc[q].z = fmaf(wj[c], t.z, acc[q].z);
                acc[q].w = fmaf(wj[c], t.w, acc[q].w);
            }
        }
    }
#pragma unroll
    for (int q = 0; q < 16; ++q) {
        outp[(size_t)(q * 4 + 0) * Vn + v] = acc[q].x;
        outp[(size_t)(q * 4 + 1) * Vn + v] = acc[q].y;
        outp[(size_t)(q * 4 + 2) * Vn + v] = acc[q].z;
        outp[(size_t)(q * 4 + 3) * Vn + v] = acc[q].w;
    }
}

// ---------------- launch ------------------------------------------------------
extern "C" void kernel_launch(void* const* d_in, const int* in_sizes, int n_in,
                              void* d_out, int out_size)
{
    const int*   seq    = (const int*)  d_in[0];
    const float* embedW = (const float*)d_in[1];
    const float* ff_w1  = (const float*)d_in[2];
    const float* ff_b1  = (const float*)d_in[3];
    const float* ff_w2  = (const float*)d_in[4];
    const float* ff_b2  = (const float*)d_in[5];
    const float* ln_g   = (const float*)d_in[6];
    const float* ln_b   = (const float*)d_in[7];
    const float* kp_w   = (const float*)d_in[8];
    const float* rp_w   = (const float*)d_in[9];
    const float* rp_b   = (const float*)d_in[10];
    const float* out_w  = (const float*)d_in[11];
    const float* out_b  = (const float*)d_in[12];
    float* outp = (float*)d_out;

    float *p_ff1, *p_x, *p_hn, *p_kt, *p_zero;
    cudaGetSymbolAddress((void**)&p_ff1,  g_ff1);
    cudaGetSymbolAddress((void**)&p_x,    g_x);
    cudaGetSymbolAddress((void**)&p_hn,   g_hn);
    cudaGetSymbolAddress((void**)&p_kt,   g_kt);
    cudaGetSymbolAddress((void**)&p_zero, g_zero);

    // vocab-table pipeline (32000 rows instead of 131072 tokens)
    sgemm_tn<true,  false><<<dim3(Vn / 128, 2), 256>>>(embedW, ff_w1, ff_b1, nullptr, p_ff1, 256, 128);
    sgemm_tn<false, true ><<<dim3(Vn / 128, 1), 256>>>(p_ff1,  ff_w2, ff_b2, embedW,  p_x,   128, 256);
    ln_kernel  <<<Vn / 8, 256>>>(ln_g, ln_b);
    sgemm_tn<false, false><<<dim3(Vn / 128, 1), 256>>>(p_hn,   kp_w,  p_zero, nullptr, p_kt,  128, 128);
    norm_kernel<<<Vn / 8, 256>>>();

    // pipelined sequential scan, one CTA per batch, M in registers
    scan_kernel<<<Bn, 256>>>(seq);

    // output head
    readrp_kernel<<<Bn, 128>>>(rp_w, rp_b);
    logits_kernel<<<Vn / 256, 256>>>(out_w, out_b, outp);
}

// round 7
// speedup vs baseline: 1.4267x; 1.4267x over previous
#include <cuda_runtime.h>
#include <math.h>
#include <stdint.h>

#define Bn 64
#define Ln 2048
#define Hn 128
#define Vn 32000

// ---------------- scratch (static device globals; no runtime allocation) ----
__device__ float  g_ff1[(size_t)Vn * 256];
__device__ float  g_x  [(size_t)Vn * Hn];
__device__ float  g_hn [(size_t)Vn * Hn];
__device__ float  g_kt [(size_t)Vn * Hn];
__device__ float  g_kn [(size_t)Vn * Hn];
__device__ float2 g_meta[Vn];            // (norm, ||kn||^2)
__device__ float  g_read[Bn * Hn];
__device__ float  g_tmp [Bn * Hn];
__device__ float  g_zero[256];           // zero-initialized: dummy bias

// packed fp32x2 FMA (Blackwell FFMA2 — only reachable via PTX fma.rn.f32x2)
__device__ __forceinline__ float2 ffma2(float2 a, float2 b, float2 c) {
    float2 d;
    asm("fma.rn.f32x2 %0, %1, %2, %3;"
        : "=l"(reinterpret_cast<unsigned long long&>(d))
        : "l"(reinterpret_cast<unsigned long long&>(a)),
          "l"(reinterpret_cast<unsigned long long&>(b)),
          "l"(reinterpret_cast<unsigned long long&>(c)));
    return d;
}

// async global->shared copies (no register landing; completion via groups)
__device__ __forceinline__ void cp_async16(void* sdst, const void* gsrc) {
    uint32_t sa = (uint32_t)__cvta_generic_to_shared(sdst);
    asm volatile("cp.async.cg.shared.global [%0], [%1], 16;" :: "r"(sa), "l"(gsrc));
}
__device__ __forceinline__ void cp_async8(void* sdst, const void* gsrc) {
    uint32_t sa = (uint32_t)__cvta_generic_to_shared(sdst);
    asm volatile("cp.async.ca.shared.global [%0], [%1], 8;" :: "r"(sa), "l"(gsrc));
}

// ---------------- generic fp32 GEMM (unchanged) ------------------------------
template <bool RELU, bool RESID>
__global__ void __launch_bounds__(256, 2) sgemm_tn(
    const float* __restrict__ A, const float* __restrict__ Bm,
    const float* __restrict__ bias, const float* __restrict__ resid,
    float* __restrict__ C, int Nn, int K)
{
    __shared__ float As[32][132];
    __shared__ float Bs[32][132];
    const int m0 = blockIdx.x * 128;
    const int n0 = blockIdx.y * 128;
    const int tid = threadIdx.x;
    const int tx = tid & 15;
    const int ty = tid >> 4;
    const int lrow = tid >> 3;       // 0..31
    const int lk   = (tid & 7) * 4;  // 0..28

    float2 acc2[8][4];
#pragma unroll
    for (int i = 0; i < 8; ++i)
#pragma unroll
        for (int j = 0; j < 4; ++j) acc2[i][j] = make_float2(0.f, 0.f);

    for (int k0 = 0; k0 < K; k0 += 32) {
#pragma unroll
        for (int p = 0; p < 4; ++p) {
            int row = lrow + p * 32;
            float4 av = *(const float4*)&A [(size_t)(m0 + row) * K + k0 + lk];
            As[lk + 0][row] = av.x; As[lk + 1][row] = av.y;
            As[lk + 2][row] = av.z; As[lk + 3][row] = av.w;
            float4 bv = *(const float4*)&Bm[(size_t)(n0 + row) * K + k0 + lk];
            Bs[lk + 0][row] = bv.x; Bs[lk + 1][row] = bv.y;
            Bs[lk + 2][row] = bv.z; Bs[lk + 3][row] = bv.w;
        }
        __syncthreads();
#pragma unroll 8
        for (int kk = 0; kk < 32; ++kk) {
            float4 a0 = *(const float4*)&As[kk][ty * 8];
            float4 a1 = *(const float4*)&As[kk][ty * 8 + 4];
            float4 b0 = *(const float4*)&Bs[kk][tx * 8];
            float4 b1 = *(const float4*)&Bs[kk][tx * 8 + 4];
            float a[8] = {a0.x, a0.y, a0.z, a0.w, a1.x, a1.y, a1.z, a1.w};
            float2 bb[4] = {make_float2(b0.x, b0.y), make_float2(b0.z, b0.w),
                            make_float2(b1.x, b1.y), make_float2(b1.z, b1.w)};
#pragma unroll
            for (int i = 0; i < 8; ++i) {
                float2 ai = make_float2(a[i], a[i]);
#pragma unroll
                for (int j = 0; j < 4; ++j)
                    acc2[i][j] = ffma2(ai, bb[j], acc2[i][j]);
            }
        }
        __syncthreads();
    }

#pragma unroll
    for (int i = 0; i < 8; ++i) {
        const int m = m0 + ty * 8 + i;
#pragma unroll
        for (int j = 0; j < 4; ++j) {
            const int n = n0 + tx * 8 + j * 2;
            float vx = acc2[i][j].x + bias[n];
            float vy = acc2[i][j].y + bias[n + 1];
            if (RELU) { vx = fmaxf(vx, 0.f); vy = fmaxf(vy, 0.f); }
            if (RESID) {
                vx += resid[(size_t)m * Nn + n];
                vy += resid[(size_t)m * Nn + n + 1];
            }
            C[(size_t)m * Nn + n]     = vx;
            C[(size_t)m * Nn + n + 1] = vy;
        }
    }
}

// ---------------- LayerNorm: one warp per row of 128 -------------------------
__global__ void __launch_bounds__(256) ln_kernel(
    const float* __restrict__ g, const float* __restrict__ bparm)
{
    const int lane = threadIdx.x & 31;
    const int row  = blockIdx.x * 8 + (threadIdx.x >> 5);
    float4 v = ((const float4*)(g_x + (size_t)row * Hn))[lane];
    float s = (v.x + v.y) + (v.z + v.w);
#pragma unroll
    for (int d = 16; d; d >>= 1) s += __shfl_xor_sync(0xffffffffu, s, d);
    const float mu = s * (1.0f / 128.0f);
    float dx = v.x - mu, dy = v.y - mu, dz = v.z - mu, dw = v.w - mu;
    float q = (dx * dx + dy * dy) + (dz * dz + dw * dw);
#pragma unroll
    for (int d = 16; d; d >>= 1) q += __shfl_xor_sync(0xffffffffu, q, d);
    const float rstd = rsqrtf(q * (1.0f / 128.0f) + 1e-5f);
    float4 gg = ((const float4*)g)[lane];
    float4 bb = ((const float4*)bparm)[lane];
    float4 o;
    o.x = fmaf(dx * rstd, gg.x, bb.x);
    o.y = fmaf(dy * rstd, gg.y, bb.y);
    o.z = fmaf(dz * rstd, gg.z, bb.z);
    o.w = fmaf(dw * rstd, gg.w, bb.w);
    ((float4*)(g_hn + (size_t)row * Hn))[lane] = o;
}

// ---------------- row normalize k-table: kn + packed meta --------------------
__global__ void __launch_bounds__(256) norm_kernel()
{
    const int lane = threadIdx.x & 31;
    const int row  = blockIdx.x * 8 + (threadIdx.x >> 5);
    float4 v = ((const float4*)(g_kt + (size_t)row * Hn))[lane];
    float q = (v.x * v.x + v.y * v.y) + (v.z * v.z + v.w * v.w);
#pragma unroll
    for (int d = 16; d; d >>= 1) q += __shfl_xor_sync(0xffffffffu, q, d);
    const float nrm = sqrtf(q);
    const float den = fmaxf(nrm, 1e-12f);
    const float inv = 1.0f / den;
    float4 o; o.x = v.x * inv; o.y = v.y * inv; o.z = v.z * inv; o.w = v.w * inv;
    ((float4*)(g_kn + (size_t)row * Hn))[lane] = o;
    if (lane == 0) g_meta[row] = make_float2(nrm, q * inv * inv);
}

// ---------------- sequential memory-matrix scan: 1 CTA per batch -------------
// R5 math (update-then-matvec, identical op order) with scheduling fixes:
//  * kn_{t+1} loaded into a 2nd reg buffer PRE-barrier (slot already published)
//  * post-barrier: gate, then FUSED update+matvec in one FFMA2 stream
//  * s_kn rows padded to 136 floats (half offset 68) -> conflict-free LDS
//  * cp.async token feed: 8-slot ring, distance 4, wait_group 2 (as R5)
#define SCAN_STEP(T, KC, KN) do {                                              \
    const int ns_ = ((T) + 1) & 7;                                             \
    float vp_ = acc + __shfl_xor_sync(0xffffffffu, acc, 1);                    \
    const float rr_ = fmaf(meta_cur.x, kv_cur, -vp_);                          \
    float e_ = rr_ * rr_;                                                      \
    e_ += __shfl_xor_sync(0xffffffffu, e_, 2);                                 \
    e_ += __shfl_xor_sync(0xffffffffu, e_, 4);                                 \
    e_ += __shfl_xor_sync(0xffffffffu, e_, 8);                                 \
    e_ += __shfl_xor_sync(0xffffffffu, e_, 16);                                \
    _Pragma("unroll")                                                          \
    for (int j_ = 0; j_ < 16; ++j_) {                                          \
        float4 v_ = *(const float4*)(s_kn[ns_] + padoff + j_ * 4);             \
        KN[2 * j_]     = make_float2(v_.x, v_.y);                              \
        KN[2 * j_ + 1] = make_float2(v_.z, v_.w);                              \
    }                                                                          \
    const float  kv_nxt_   = s_kn[ns_][kvidx];                                 \
    const float2 meta_nxt_ = s_meta[ns_];                                      \
    if (lane == 0) s_part[(T) & 1][wid] = e_;                                  \
    if (tid < 32) {                                                            \
        if ((T) + 4 < Ln) {                                                    \
            const int pb_  = ((T) + 4) & 7;                                    \
            const int tok_ = s_seq[(T) + 4];                                   \
            cp_async16(&s_kn[pb_][(tid >> 4) * 68 + (tid & 15) * 4],           \
                       g_kn + (size_t)tok_ * Hn + tid * 4);                    \
            if (tid == 0) cp_async8(&s_meta[pb_], g_meta + tok_);              \
        }                                                                      \
        asm volatile("cp.async.commit_group;" ::: "memory");                   \
        asm volatile("cp.async.wait_group 2;" ::: "memory");                   \
    }                                                                          \
    __syncthreads();                                                           \
    float4 p0_ = ((const float4*)s_part[(T) & 1])[0];                          \
    float4 p1_ = ((const float4*)s_part[(T) & 1])[1];                          \
    float tot_ = ((p0_.x + p0_.y) + (p0_.z + p0_.w))                           \
               + ((p1_.x + p1_.y) + (p1_.z + p1_.w));                          \
    float2 a0_ = make_float2(0.f, 0.f), a1_ = a0_, a2_ = a0_, a3_ = a0_;       \
    if (tot_ * meta_cur.y * (1.0f / 16384.0f) >= 0.4f) {                       \
        const float2 rr2_ = make_float2(rr_, rr_);                             \
        _Pragma("unroll")                                                      \
        for (int j_ = 0; j_ < 32; j_ += 4) {                                   \
            M2[j_ + 0] = ffma2(rr2_, KC[j_ + 0], M2[j_ + 0]);                  \
            a0_ = ffma2(M2[j_ + 0], KN[j_ + 0], a0_);                          \
            M2[j_ + 1] = ffma2(rr2_, KC[j_ + 1], M2[j_ + 1]);                  \
            a1_ = ffma2(M2[j_ + 1], KN[j_ + 1], a1_);                          \
            M2[j_ + 2] = ffma2(rr2_, KC[j_ + 2], M2[j_ + 2]);                  \
            a2_ = ffma2(M2[j_ + 2], KN[j_ + 2], a2_);                          \
            M2[j_ + 3] = ffma2(rr2_, KC[j_ + 3], M2[j_ + 3]);                  \
            a3_ = ffma2(M2[j_ + 3], KN[j_ + 3], a3_);                          \
        }                                                                      \
    } else {                                                                   \
        _Pragma("unroll")                                                      \
        for (int j_ = 0; j_ < 32; j_ += 4) {                                   \
            a0_ = ffma2(M2[j_ + 0], KN[j_ + 0], a0_);                          \
            a1_ = ffma2(M2[j_ + 1], KN[j_ + 1], a1_);                          \
            a2_ = ffma2(M2[j_ + 2], KN[j_ + 2], a2_);                          \
            a3_ = ffma2(M2[j_ + 3], KN[j_ + 3], a3_);                          \
        }                                                                      \
    }                                                                          \
    acc = ((a0_.x + a0_.y) + (a1_.x + a1_.y))                                  \
        + ((a2_.x + a2_.y) + (a3_.x + a3_.y));                                 \
    kv_cur = kv_nxt_; meta_cur = meta_nxt_;                                    \
} while (0)

__global__ void __launch_bounds__(256, 1) scan_kernel(const int* __restrict__ seq)
{
    __shared__ __align__(16) float  s_kn[8][136];   // padded: half offset 68
    __shared__ __align__(16) float2 s_meta[8];
    __shared__ int   s_seq[Ln];
    __shared__ __align__(16) float s_part[2][8];

    const int b    = blockIdx.x;
    const int tid  = threadIdx.x;
    const int r    = tid >> 1;
    const int hh   = tid & 1;
    const int padoff = hh * 68;
    const int kvidx  = (r >> 6) * 68 + (r & 63);
    const int lane = tid & 31;
    const int wid  = tid >> 5;

    for (int i = tid; i < Ln; i += 256) s_seq[i] = seq[(size_t)b * Ln + i];

    float2 M2[32];
#pragma unroll
    for (int j = 0; j < 32; ++j) M2[j] = make_float2(0.f, 0.f);
    __syncthreads();

    // prologue: preload ring slots 0..3 (tokens 0..3), padded layout
    if (tid < 128) {
        int slot = tid >> 5, c = tid & 31;
        int hhp = c >> 4, jp = c & 15;
        int tok = s_seq[slot];
        *(float4*)(s_kn[slot] + hhp * 68 + jp * 4) =
            ((const float4*)(g_kn + (size_t)tok * Hn))[c];
    }
    if (tid < 4) s_meta[tid] = g_meta[s_seq[tid]];
    __syncthreads();

    // kn_0 into ka; M=0 so acc (=M.kn_0 partial) starts at 0
    float2 ka[32], kb[32];
#pragma unroll
    for (int j = 0; j < 16; ++j) {
        float4 v = *(const float4*)(s_kn[0] + padoff + j * 4);
        ka[2 * j]     = make_float2(v.x, v.y);
        ka[2 * j + 1] = make_float2(v.z, v.w);
    }
    float  acc      = 0.f;
    float  kv_cur   = s_kn[0][kvidx];
    float2 meta_cur = s_meta[0];

    // Ln-1 = 2047 steps: 1023 pairs + 1 tail step (even t uses ka as current)
    for (int t = 0; t + 1 < Ln - 1; t += 2) {
        SCAN_STEP(t,     ka, kb);
        SCAN_STEP(t + 1, kb, ka);
    }
    SCAN_STEP(Ln - 2, ka, kb);   // t = 2046 (even): current=ka, next->kb

    // epilogue: acc = M_final . kn_{Ln-1}; read = (M q)_r with q = kn*norm
    {
        float vp = acc + __shfl_xor_sync(0xffffffffu, acc, 1);
        if (hh == 0) g_read[b * Hn + r] = vp * meta_cur.x;
    }
}

// ---------------- tmp = read @ rp_w^T + rp_b ---------------------------------
__global__ void __launch_bounds__(128) readrp_kernel(
    const float* __restrict__ rp_w, const float* __restrict__ rp_b)
{
    __shared__ float s_r[128];
    const int b = blockIdx.x;
    s_r[threadIdx.x] = g_read[b * Hn + threadIdx.x];
    __syncthreads();
    const int n = threadIdx.x;
    const float* wrow = rp_w + (size_t)n * Hn;
    float a0 = 0.f, a1 = 0.f, a2 = 0.f, a3 = 0.f;
#pragma unroll 8
    for (int j = 0; j < 128; j += 4) {
        a0 = fmaf(s_r[j + 0], wrow[j + 0], a0);
        a1 = fmaf(s_r[j + 1], wrow[j + 1], a1);
        a2 = fmaf(s_r[j + 2], wrow[j + 2], a2);
        a3 = fmaf(s_r[j + 3], wrow[j + 3], a3);
    }
    g_tmp[b * Hn + n] = (a0 + a1) + (a2 + a3) + rp_b[n];
}

// ---------------- logits: out[b][v] = tmp[b][:] . out_w[v][:] + out_b[v] -----
__global__ void __launch_bounds__(256) logits_kernel(
    const float* __restrict__ out_w, const float* __restrict__ out_b,
    float* __restrict__ outp)
{
    __shared__ __align__(16) float s_t[128][64];  // [j][b]
    for (int i = threadIdx.x; i < Bn * Hn; i += 256) {
        int b = i >> 7, j = i & 127;
        s_t[j][b] = g_tmp[i];
    }
    __syncthreads();

    const int v = blockIdx.x * 256 + threadIdx.x;
    const float4* wr = (const float4*)(out_w + (size_t)v * Hn);
    const float ob = out_b[v];
    float4 acc[16];
#pragma unroll
    for (int q = 0; q < 16; ++q) acc[q] = make_float4(ob, ob, ob, ob);

    for (int j4 = 0; j4 < 32; ++j4) {
        float4 w = wr[j4];
        float wj[4] = {w.x, w.y, w.z, w.w};
#pragma unroll
        for (int c = 0; c < 4; ++c) {
            const float4* tp = (const float4*)s_t[j4 * 4 + c];
#pragma unroll
            for (int q = 0; q < 16; ++q) {
                float4 t = tp[q];
                acc[q].x = fmaf(wj[c], t.x, acc[q].x);
                acc[q].y = fmaf(wj[c], t.y, acc[q].y);
                acc[q].z = fmaf(wj[c], t.z, acc[q].z);
                acc[q].w = fmaf(wj[c], t.w, acc[q].w);
            }
        }
    }
#pragma unroll
    for (int q = 0; q < 16; ++q) {
        outp[(size_t)(q * 4 + 0) * Vn + v] = acc[q].x;
        outp[(size_t)(q * 4 + 1) * Vn + v] = acc[q].y;
        outp[(size_t)(q * 4 + 2) * Vn + v] = acc[q].z;
        outp[(size_t)(q * 4 + 3) * Vn + v] = acc[q].w;
    }
}

// ---------------- launch ------------------------------------------------------
extern "C" void kernel_launch(void* const* d_in, const int* in_sizes, int n_in,
                              void* d_out, int out_size)
{
    const int*   seq    = (const int*)  d_in[0];
    const float* embedW = (const float*)d_in[1];
    const float* ff_w1  = (const float*)d_in[2];
    const float* ff_b1  = (const float*)d_in[3];
    const float* ff_w2  = (const float*)d_in[4];
    const float* ff_b2  = (const float*)d_in[5];
    const float* ln_g   = (const float*)d_in[6];
    const float* ln_b   = (const float*)d_in[7];
    const float* kp_w   = (const float*)d_in[8];
    const float* rp_w   = (const float*)d_in[9];
    const float* rp_b   = (const float*)d_in[10];
    const float* out_w  = (const float*)d_in[11];
    const float* out_b  = (const float*)d_in[12];
    float* outp = (float*)d_out;

    float *p_ff1, *p_x, *p_hn, *p_kt, *p_zero;
    cudaGetSymbolAddress((void**)&p_ff1,  g_ff1);
    cudaGetSymbolAddress((void**)&p_x,    g_x);
    cudaGetSymbolAddress((void**)&p_hn,   g_hn);
    cudaGetSymbolAddress((void**)&p_kt,   g_kt);
    cudaGetSymbolAddress((void**)&p_zero, g_zero);

    // vocab-table pipeline (32000 rows instead of 131072 tokens)
    sgemm_tn<true,  false><<<dim3(Vn / 128, 2), 256>>>(embedW, ff_w1, ff_b1, nullptr, p_ff1, 256, 128);
    sgemm_tn<false, true ><<<dim3(Vn / 128, 1), 256>>>(p_ff1,  ff_w2, ff_b2, embedW,  p_x,   128, 256);
    ln_kernel  <<<Vn / 8, 256>>>(ln_g, ln_b);
    sgemm_tn<false, false><<<dim3(Vn / 128, 1), 256>>>(p_hn,   kp_w,  p_zero, nullptr, p_kt,  128, 128);
    norm_kernel<<<Vn / 8, 256>>>();

    // sequential scan, one CTA per batch, M in registers, fused update+matvec
    scan_kernel<<<Bn, 256>>>(seq);

    // output head
    readrp_kernel<<<Bn, 128>>>(rp_w, rp_b);
    logits_kernel<<<Vn / 256, 256>>>(out_w, out_b, outp);
}